// round 3
// baseline (speedup 1.0000x reference)
#include <cuda_runtime.h>

#define S_     7
#define SS_    49
#define BATCH_ 16384
#define D_     30
#define NCELL_ (BATCH_ * SS_)          /* 802816 */
#define CPB_   128                     /* cells per block */
#define BLK_   128                     /* threads per block */
#define NBLK1_ (NCELL_ / CPB_)         /* 6272 */
#define TILE_W (CPB_ * D_)             /* 3840 floats per tensor tile */
#define TILE_V (TILE_W / 4)            /* 960 float4 */

__device__ float g_A[SS_];
__device__ float g_C;
__device__ float g_has[NCELL_];

__device__ __forceinline__ float scalar_to_float(const void* p) {
    int v = *(const int*)p;
    if (v > 0 && v < 1000000) return (float)v;   /* plausible int32 */
    return __int_as_float(v);                    /* actually float32 bits */
}

__device__ __forceinline__ float iou_fn(float cx, float cy, float w, float h,
                                        float tx0, float ty0, float tx1, float ty1,
                                        float areaT) {
    float hw = w * 0.5f, hh = h * 0.5f;
    float x0 = cx - hw, x1 = cx + hw;
    float y0 = cy - hh, y1 = cy + hh;
    float iw = fmaxf(fminf(x1, tx1) - fmaxf(x0, tx0), 0.0f);
    float ih = fmaxf(fminf(y1, ty1) - fmaxf(y0, ty0), 0.0f);
    float inter = iw * ih;
    float area_a = (x1 - x0) * (y1 - y0);
    return inter / (area_a + areaT - inter + 1e-9f);
}

__global__ void init_kernel() {
    int t = threadIdx.x;
    if (t < SS_) g_A[t] = 0.0f;
    if (t == 0) g_C = 0.0f;
}

__global__ __launch_bounds__(BLK_) void pass1_kernel(
    const float* __restrict__ outp, const float* __restrict__ tgt,
    const void* __restrict__ iwp, const void* __restrict__ ihp)
{
    __shared__ float so[TILE_W];       /* output tile, linear layout */
    __shared__ float st[TILE_W];       /* target tile, linear layout */
    __shared__ float sA[SS_];
    __shared__ float sC;

    const float W = scalar_to_float(iwp);
    const float H = scalar_to_float(ihp);
    const float csx = W / 7.0f, csy = H / 7.0f;

    const int tid = threadIdx.x;
    const int cell0 = blockIdx.x * CPB_;

    /* ---- stage: coalesced float4 loads ---- */
    const float4* go4 = (const float4*)(outp + (size_t)cell0 * D_);
    const float4* gt4 = (const float4*)(tgt  + (size_t)cell0 * D_);
    float4* so4 = (float4*)so;
    float4* st4 = (float4*)st;
#pragma unroll
    for (int i = 0; i < 8; i++) {
        int idx = i * BLK_ + tid;
        if (idx < TILE_V) {
            so4[idx] = go4[idx];
            st4[idx] = gt4[idx];
        }
    }
    if (tid < SS_) sA[tid] = 0.0f;
    if (tid == 64) sC = 0.0f;
    __syncthreads();

    /* ---- compute: one cell per thread ---- */
    const int cell = cell0 + tid;
    const int rc = cell % SS_;
    const float rr = (float)(rc / S_);
    const float cc = (float)(rc % S_);

    const float2* o2 = (const float2*)(so + tid * D_);   /* 30*tid even -> 8B aligned */
    const float2* t2 = (const float2*)(st + tid * D_);

    float2 oa = o2[0], ob = o2[1], oc = o2[2], od = o2[3], oe = o2[4];
    float2 ta = t2[0], tb = t2[1], tc = t2[2];

    float o0 = oa.x, o1 = oa.y, o3 = ob.y, o4 = oc.x;
    float o5 = oc.y, o6 = od.x, o8 = oe.x, o9 = oe.y;

    float tx = ta.x, ty = ta.y;
    float tw = tb.x * W, th = tb.y * H;
    float has = tc.x;

    /* target box */
    float cxt = (cc + tx) * csx, cyt = (rr + ty) * csy;
    float htw = tw * 0.5f, hth = th * 0.5f;
    float tx0 = cxt - htw, tx1 = cxt + htw;
    float ty0 = cyt - hth, ty1 = cyt + hth;
    float areaT = (tx1 - tx0) * (ty1 - ty0);

    float iou0 = iou_fn((cc + o0) * csx, (rr + o1) * csy, o3 * W, o4 * H,
                        tx0, ty0, tx1, ty1, areaT);
    float iou1 = iou_fn((cc + o5) * csx, (rr + o6) * csy, o8 * W, o9 * H,
                        tx0, ty0, tx1, ty1, areaT);

    /* best = LAST argmax (reference reverses before argmax) */
    float bc = (iou1 >= iou0) ? o9 : o4;

    /* class term: channels 10..29 */
    float cls = 0.0f;
#pragma unroll
    for (int k = 0; k < 10; k++) {
        float2 ock = o2[5 + k];
        float2 tck = t2[5 + k];
        float d0 = tck.x - ock.x * bc;
        float d1 = tck.y - ock.y * bc;
        cls += d0 * d0 + d1 * d1;
    }

    /* last predictor coordinate + conf terms */
    float dx  = tx - o5;
    float dy  = ty - o6;
    float swd = sqrtf(tw) - sqrtf(o8 * W);
    float shd = sqrtf(th) - sqrtf(o9 * H);
    float dcf = has - o9;
    float confsq = dcf * dcf;

    float accA = 5.0f * (dx * dx + dy * dy + swd * swd + shd * shd) + 0.5f * confsq;
    float accC = 0.5f * confsq + cls;

    g_has[cell] = has;                 /* coalesced 4B store */

    /* ---- block reduction ---- */
    atomicAdd(&sA[rc], accA);
#pragma unroll
    for (int off = 16; off > 0; off >>= 1)
        accC += __shfl_down_sync(0xFFFFFFFFu, accC, off);
    if ((tid & 31) == 0) atomicAdd(&sC, accC);
    __syncthreads();

    if (tid < SS_) atomicAdd(&g_A[tid], sA[tid]);
    if (tid == 64) atomicAdd(&g_C, sC);
}

__global__ __launch_bounds__(256) void pass2_kernel(float* __restrict__ out)
{
    __shared__ float sA[SS_];
    __shared__ float sC;
    if (threadIdx.x < SS_) sA[threadIdx.x] = g_A[threadIdx.x];
    if (threadIdx.x == 64) sC = g_C;
    __syncthreads();

    int b = blockIdx.x * 256 + threadIdx.x;
    const float* hb = g_has + (size_t)b * SS_;
    float s = 0.0f;
#pragma unroll
    for (int rc = 0; rc < SS_; rc++)
        s += hb[rc] * sA[rc];
    out[b] = s + sC;
}

extern "C" void kernel_launch(void* const* d_in, const int* in_sizes, int n_in,
                              void* d_out, int out_size)
{
    const float* o  = (const float*)d_in[0];
    const float* t  = (const float*)d_in[1];
    const void*  iw = d_in[2];
    const void*  ih = d_in[3];

    init_kernel<<<1, 64>>>();
    pass1_kernel<<<NBLK1_, BLK_>>>(o, t, iw, ih);
    pass2_kernel<<<BATCH_ / 256, 256>>>((float*)d_out);
}

// round 4
// speedup vs baseline: 1.0442x; 1.0442x over previous
#include <cuda_runtime.h>

#define S_     7
#define SS_    49
#define BATCH_ 16384
#define D_     30
#define NCELL_ (BATCH_ * SS_)          /* 802816 */
#define CPB_   128                     /* cells per block */
#define BLK_   192                     /* threads per block (copy: 960/192 = 5 exact) */
#define NBLK1_ (NCELL_ / CPB_)         /* 6272 */
#define TILE_W (CPB_ * D_)             /* 3840 floats per tensor tile */
#define TILE_V (TILE_W / 4)            /* 960 float4 */
#define NBLK2_ 64                      /* pass2 blocks (16384/256) */

__device__ float g_A[SS_];
__device__ float g_C;
__device__ float g_has[NCELL_];
__device__ int   g_counter;            /* static-init 0; self-resets each replay */

__device__ __forceinline__ float scalar_to_float(const void* p) {
    int v = *(const int*)p;
    if (v > 0 && v < 1000000) return (float)v;   /* plausible int32 */
    return __int_as_float(v);                    /* actually float32 bits */
}

__device__ __forceinline__ float iou_fn(float cx, float cy, float w, float h,
                                        float tx0, float ty0, float tx1, float ty1,
                                        float areaT) {
    float hw = w * 0.5f, hh = h * 0.5f;
    float x0 = cx - hw, x1 = cx + hw;
    float y0 = cy - hh, y1 = cy + hh;
    float iw = fmaxf(fminf(x1, tx1) - fmaxf(x0, tx0), 0.0f);
    float ih = fmaxf(fminf(y1, ty1) - fmaxf(y0, ty0), 0.0f);
    float inter = iw * ih;
    float area_a = (x1 - x0) * (y1 - y0);
    return inter / (area_a + areaT - inter + 1e-9f);
}

__global__ __launch_bounds__(BLK_) void pass1_kernel(
    const float* __restrict__ outp, const float* __restrict__ tgt,
    const void* __restrict__ iwp, const void* __restrict__ ihp)
{
    __shared__ float so[TILE_W];
    __shared__ float st[TILE_W];
    __shared__ float sA[SS_];
    __shared__ float sC;

    const float W = scalar_to_float(iwp);
    const float H = scalar_to_float(ihp);
    const float csx = W / 7.0f, csy = H / 7.0f;

    const int tid = threadIdx.x;
    const int cell0 = blockIdx.x * CPB_;

    /* ---- stage: coalesced float4 loads, exactly 5 iters, no predicate ---- */
    const float4* go4 = (const float4*)(outp + (size_t)cell0 * D_);
    const float4* gt4 = (const float4*)(tgt  + (size_t)cell0 * D_);
    float4* so4 = (float4*)so;
    float4* st4 = (float4*)st;
#pragma unroll
    for (int i = 0; i < 5; i++) {
        int idx = i * BLK_ + tid;
        so4[idx] = go4[idx];
        st4[idx] = gt4[idx];
    }
    if (tid < SS_) sA[tid] = 0.0f;
    if (tid == 64) sC = 0.0f;
    __syncthreads();

    /* ---- compute: one cell per thread, threads 128..191 idle ---- */
    if (tid < CPB_) {
        const int cell = cell0 + tid;
        const int rc = cell % SS_;
        const float rr = (float)(rc / S_);
        const float cc = (float)(rc % S_);

        const float2* o2 = (const float2*)(so + tid * D_);
        const float2* t2 = (const float2*)(st + tid * D_);

        float2 oa = o2[0], ob = o2[1], oc = o2[2], od = o2[3], oe = o2[4];
        float2 ta = t2[0], tb = t2[1], tc = t2[2];

        float o0 = oa.x, o1 = oa.y, o3 = ob.y, o4 = oc.x;
        float o5 = oc.y, o6 = od.x, o8 = oe.x, o9 = oe.y;

        float tx = ta.x, ty = ta.y;
        float tw = tb.x * W, th = tb.y * H;
        float has = tc.x;

        float cxt = (cc + tx) * csx, cyt = (rr + ty) * csy;
        float htw = tw * 0.5f, hth = th * 0.5f;
        float tx0 = cxt - htw, tx1 = cxt + htw;
        float ty0 = cyt - hth, ty1 = cyt + hth;
        float areaT = (tx1 - tx0) * (ty1 - ty0);

        float iou0 = iou_fn((cc + o0) * csx, (rr + o1) * csy, o3 * W, o4 * H,
                            tx0, ty0, tx1, ty1, areaT);
        float iou1 = iou_fn((cc + o5) * csx, (rr + o6) * csy, o8 * W, o9 * H,
                            tx0, ty0, tx1, ty1, areaT);

        float bc = (iou1 >= iou0) ? o9 : o4;   /* last argmax per reference */

        float cls = 0.0f;
#pragma unroll
        for (int k = 0; k < 10; k++) {
            float2 ock = o2[5 + k];
            float2 tck = t2[5 + k];
            float d0 = tck.x - ock.x * bc;
            float d1 = tck.y - ock.y * bc;
            cls += d0 * d0 + d1 * d1;
        }

        float dx  = tx - o5;
        float dy  = ty - o6;
        float swd = sqrtf(tw) - sqrtf(o8 * W);
        float shd = sqrtf(th) - sqrtf(o9 * H);
        float dcf = has - o9;
        float confsq = dcf * dcf;

        float accA = 5.0f * (dx * dx + dy * dy + swd * swd + shd * shd) + 0.5f * confsq;
        float accC = 0.5f * confsq + cls;

        g_has[cell] = has;

        atomicAdd(&sA[rc], accA);
#pragma unroll
        for (int off = 16; off > 0; off >>= 1)
            accC += __shfl_down_sync(0xFFFFFFFFu, accC, off);
        if ((tid & 31) == 0) atomicAdd(&sC, accC);
    }
    __syncthreads();

    if (tid < SS_) atomicAdd(&g_A[tid], sA[tid]);
    if (tid == 64) atomicAdd(&g_C, sC);
}

__global__ __launch_bounds__(256) void pass2_kernel(float* __restrict__ out)
{
    __shared__ float sA[SS_];
    __shared__ float sC;
    if (threadIdx.x < SS_) sA[threadIdx.x] = g_A[threadIdx.x];
    if (threadIdx.x == 64) sC = g_C;
    __syncthreads();   /* all reads of g_A/g_C latched into smem */

    /* last block to arrive zeroes the accumulators for the next replay */
    if (threadIdx.x == 0) {
        int old = atomicAdd(&g_counter, 1);
        if (old == NBLK2_ - 1) {
#pragma unroll
            for (int i = 0; i < SS_; i++) g_A[i] = 0.0f;
            g_C = 0.0f;
            g_counter = 0;
        }
    }

    int b = blockIdx.x * 256 + threadIdx.x;
    const float* hb = g_has + (size_t)b * SS_;
    float s = 0.0f;
#pragma unroll
    for (int rc = 0; rc < SS_; rc++)
        s += hb[rc] * sA[rc];
    out[b] = s + sC;
}

extern "C" void kernel_launch(void* const* d_in, const int* in_sizes, int n_in,
                              void* d_out, int out_size)
{
    const float* o  = (const float*)d_in[0];
    const float* t  = (const float*)d_in[1];
    const void*  iw = d_in[2];
    const void*  ih = d_in[3];

    pass1_kernel<<<NBLK1_, BLK_>>>(o, t, iw, ih);
    pass2_kernel<<<NBLK2_, 256>>>((float*)d_out);
}

// round 6
// speedup vs baseline: 1.1530x; 1.1043x over previous
#include <cuda_runtime.h>

#define S_      7
#define SS_     49
#define BATCH_  16384
#define D_      30
#define NCELL_  (BATCH_ * SS_)         /* 802816 */
#define CPB_    128                    /* cells per tile */
#define BLK_    192                    /* threads per block */
#define NBLK_   448                    /* persistent blocks; 448*14 = 6272 tiles */
#define TPB_    14                     /* tiles per block */
#define TILE_W  (CPB_ * D_)            /* 3840 floats */
#define LPT_    5                      /* float4 per thread per array (960/192) */
#define OUT_BLKS_ 128                  /* blocks doing the output phase */
#define BPO_    128                    /* batches per output block */
#define OUT_V   (BPO_ * SS_ / 4)       /* 1568 float4 of has per out block */

__device__ float g_A[SS_];
__device__ float g_C;
__device__ float g_has[NCELL_];
__device__ int   g_barrier;            /* static 0; self-resets each call */
__device__ int   g_done;               /* static 0; self-resets each call */

__device__ __forceinline__ float scalar_to_float(const void* p) {
    int v = *(const int*)p;
    if (v > 0 && v < 1000000) return (float)v;   /* plausible int32 */
    return __int_as_float(v);                    /* actually float32 bits */
}

__device__ __forceinline__ float iou_fn(float cx, float cy, float w, float h,
                                        float tx0, float ty0, float tx1, float ty1,
                                        float areaT) {
    float hw = w * 0.5f, hh = h * 0.5f;
    float x0 = cx - hw, x1 = cx + hw;
    float y0 = cy - hh, y1 = cy + hh;
    float iw = fmaxf(fminf(x1, tx1) - fmaxf(x0, tx0), 0.0f);
    float ih = fmaxf(fminf(y1, ty1) - fmaxf(y0, ty0), 0.0f);
    float inter = iw * ih;
    float area_a = (x1 - x0) * (y1 - y0);
    return inter / (area_a + areaT - inter + 1e-9f);
}

__global__ __launch_bounds__(BLK_, 4) void yolo_kernel(
    const float* __restrict__ outp, const float* __restrict__ tgt,
    const void* __restrict__ iwp, const void* __restrict__ ihp,
    float* __restrict__ lossOut)
{
    __shared__ __align__(16) float pool[TILE_W * 2];   /* so|st, later sHas */
    __shared__ float sA_blk[SS_];
    __shared__ float sC_blk;
    __shared__ float sAfin[SS_ + 1];

    const float W = scalar_to_float(iwp);
    const float H = scalar_to_float(ihp);
    const float csx = W / 7.0f, csy = H / 7.0f;

    const int tid = threadIdx.x;
    float* so = pool;
    float* st = pool + TILE_W;

    if (tid < SS_) sA_blk[tid] = 0.0f;
    if (tid == 64) sC_blk = 0.0f;

    /* ---------------- phase 1: streaming accumulation ---------------- */
    const int tile0 = blockIdx.x * TPB_;
    float4 ro[LPT_], rt[LPT_];

    {   /* prefetch tile 0 */
        const float4* go4 = (const float4*)(outp + (size_t)tile0 * CPB_ * D_);
        const float4* gt4 = (const float4*)(tgt  + (size_t)tile0 * CPB_ * D_);
#pragma unroll
        for (int j = 0; j < LPT_; j++) {
            int idx = j * BLK_ + tid;
            ro[j] = go4[idx];
            rt[j] = gt4[idx];
        }
    }

    float accC = 0.0f;

    for (int i = 0; i < TPB_; i++) {
        float4* so4 = (float4*)so;
        float4* st4 = (float4*)st;
#pragma unroll
        for (int j = 0; j < LPT_; j++) {
            int idx = j * BLK_ + tid;
            so4[idx] = ro[j];
            st4[idx] = rt[j];
        }
        __syncthreads();

        /* prefetch next tile while computing this one */
        if (i + 1 < TPB_) {
            const float4* go4 = (const float4*)(outp + (size_t)(tile0 + i + 1) * CPB_ * D_);
            const float4* gt4 = (const float4*)(tgt  + (size_t)(tile0 + i + 1) * CPB_ * D_);
#pragma unroll
            for (int j = 0; j < LPT_; j++) {
                int idx = j * BLK_ + tid;
                ro[j] = go4[idx];
                rt[j] = gt4[idx];
            }
        }

        if (tid < CPB_) {
            const int cell = (tile0 + i) * CPB_ + tid;
            const int rc = cell % SS_;
            const float rr = (float)(rc / S_);
            const float cc = (float)(rc % S_);

            const float2* o2 = (const float2*)(so + tid * D_);
            const float2* t2 = (const float2*)(st + tid * D_);

            float2 oa = o2[0], ob = o2[1], oc = o2[2], od = o2[3], oe = o2[4];
            float2 ta = t2[0], tb = t2[1], tc = t2[2];

            float o0 = oa.x, o1 = oa.y, o3 = ob.y, o4 = oc.x;
            float o5 = oc.y, o6 = od.x, o8 = oe.x, o9 = oe.y;

            float tx = ta.x, ty = ta.y;
            float tw = tb.x * W, th = tb.y * H;
            float has = tc.x;

            float cxt = (cc + tx) * csx, cyt = (rr + ty) * csy;
            float htw = tw * 0.5f, hth = th * 0.5f;
            float tx0 = cxt - htw, tx1 = cxt + htw;
            float ty0 = cyt - hth, ty1 = cyt + hth;
            float areaT = (tx1 - tx0) * (ty1 - ty0);

            float iou0 = iou_fn((cc + o0) * csx, (rr + o1) * csy, o3 * W, o4 * H,
                                tx0, ty0, tx1, ty1, areaT);
            float iou1 = iou_fn((cc + o5) * csx, (rr + o6) * csy, o8 * W, o9 * H,
                                tx0, ty0, tx1, ty1, areaT);

            float bc = (iou1 >= iou0) ? o9 : o4;   /* last argmax per reference */

            float cls = 0.0f;
#pragma unroll
            for (int k = 0; k < 10; k++) {
                float2 ock = o2[5 + k];
                float2 tck = t2[5 + k];
                float d0 = tck.x - ock.x * bc;
                float d1 = tck.y - ock.y * bc;
                cls += d0 * d0 + d1 * d1;
            }

            float dx  = tx - o5;
            float dy  = ty - o6;
            float swd = sqrtf(tw) - sqrtf(o8 * W);
            float shd = sqrtf(th) - sqrtf(o9 * H);
            float dcf = has - o9;
            float confsq = dcf * dcf;

            float accA = 5.0f * (dx * dx + dy * dy + swd * swd + shd * shd)
                       + 0.5f * confsq;
            accC += 0.5f * confsq + cls;

            g_has[cell] = has;
            atomicAdd(&sA_blk[rc], accA);
        }
        __syncthreads();
    }

    /* block reduction of C (warps 4,5 contribute zeros) */
#pragma unroll
    for (int off = 16; off > 0; off >>= 1)
        accC += __shfl_down_sync(0xFFFFFFFFu, accC, off);
    if ((tid & 31) == 0) atomicAdd(&sC_blk, accC);
    __syncthreads();

    if (tid < SS_) atomicAdd(&g_A[tid], sA_blk[tid]);
    if (tid == 64) atomicAdd(&g_C, sC_blk);

    /* ---------------- grid-wide barrier ---------------- */
    __threadfence();                       /* EVERY thread: g_has stores visible device-wide */
    __syncthreads();                       /* all this block's fences done */
    if (tid == 0) {
        atomicAdd(&g_barrier, 1);
        while (*(volatile int*)&g_barrier < NBLK_) { __nanosleep(64); }
    }
    __syncthreads();

    /* ---------------- phase 2: per-batch outputs ---------------- */
    int arrive_old;
    if (blockIdx.x < OUT_BLKS_) {
        if (tid < SS_) sAfin[tid] = g_A[tid];
        if (tid == 64) sAfin[SS_] = g_C;

        const float4* gh4 = (const float4*)(g_has + (size_t)blockIdx.x * BPO_ * SS_);
        float4* sh4 = (float4*)pool;
#pragma unroll
        for (int j = 0; j < 9; j++) {
            int idx = j * BLK_ + tid;
            if (idx < OUT_V) sh4[idx] = gh4[idx];
        }
        __syncthreads();                   /* latch + stage complete */

        if (tid == 0) arrive_old = atomicAdd(&g_done, 1);

        if (tid < BPO_) {
            const float* hb = pool + tid * SS_;   /* stride 49: conflict-free */
            float s = 0.0f;
#pragma unroll
            for (int rc = 0; rc < SS_; rc++)
                s += hb[rc] * sAfin[rc];
            lossOut[blockIdx.x * BPO_ + tid] = s + sAfin[SS_];
        }
    } else {
        if (tid == 0) arrive_old = atomicAdd(&g_done, 1);
    }

    /* last arriving block resets accumulators for the next replay */
    if (tid == 0 && arrive_old == NBLK_ - 1) {
#pragma unroll
        for (int i = 0; i < SS_; i++) g_A[i] = 0.0f;
        g_C = 0.0f;
        g_barrier = 0;
        g_done = 0;
    }
}

extern "C" void kernel_launch(void* const* d_in, const int* in_sizes, int n_in,
                              void* d_out, int out_size)
{
    const float* o  = (const float*)d_in[0];
    const float* t  = (const float*)d_in[1];
    const void*  iw = d_in[2];
    const void*  ih = d_in[3];

    yolo_kernel<<<NBLK_, BLK_>>>(o, t, iw, ih, (float*)d_out);
}